// round 4
// baseline (speedup 1.0000x reference)
#include <cuda_runtime.h>
#include <cuda_bf16.h>
#include <cuda_fp16.h>

#define Bn 128
#define Vn 1024
#define Tn 1024
#define Cn 1024
#define VT 16   // v-columns per CTA in the attention kernel (8 warps x 2 cols)

// Scratch (allocation-free rule: __device__ globals)
__device__ float g_vs[Bn * Tn];   // visual_score, atomically accumulated (zeroed each launch)
__device__ float g_ts[Bn * Vn];   // text_score, written exactly once
__device__ float g_acc[Bn * Cn];  // GEMM split-K accumulator (zeroed each launch)

__device__ __forceinline__ float fex2_approx(float x) {
    float r;
    asm("ex2.approx.f32 %0, %1;" : "=f"(r) : "f"(x));
    return r;
}

__device__ __forceinline__ float ftanh_approx(float x) {
    float r;
    asm("tanh.approx.f32 %0, %1;" : "=f"(r) : "f"(x));
    return r;
}

// ---------------------------------------------------------------------------
// Kernel 1: fused scores/tanh/softmax/reductions.
// Grid: (Vn/VT, Bn). Block: 256 threads (8 warps, 2 v-columns per warp).
// Pass 1: E = exp(tanh(s)) -> half2 slab (col pair per warp); Z + text numer.
// Pass 2: visual partials from half2 slab, atomicAdd into g_vs.
// SMEM: e 32KB + wy 8KB + g 64B  -> 4 CTAs/SM.
// ---------------------------------------------------------------------------
extern __shared__ float smem_dyn[];

__global__ __launch_bounds__(256, 4) void attn_pass_kernel(
    const float* __restrict__ vis,     // [B, V]
    const float* __restrict__ txt,     // [B, T]
    const float* __restrict__ w_vis,   // [T]
    const float* __restrict__ w_text,  // [V]
    const float* __restrict__ bias)    // [V]
{
    __half2* e  = (__half2*)smem_dyn;                    // 8 rows (warp) x Tn
    float2*  wy = (float2*)(smem_dyn + 2 * 4096);        // Tn float2 (w, y)
    float*   g  = (float*)(wy + Tn);                     // VT floats

    const int b   = blockIdx.y;
    const int v0  = blockIdx.x * VT;
    const int tid = threadIdx.x;

    for (int i = tid; i < Tn; i += 256)
        wy[i] = make_float2(w_vis[i], txt[b * Tn + i]);
    __syncthreads();

    const int warp = tid >> 5;
    const int lane = tid & 31;
    const int vl   = warp * 2;  // local v base for this warp

    const float L2E = 1.4426950408889634f;   // log2(e)

    float x0, x1, c0, c1, bv0, bv1;
    {
        int vg = v0 + vl;
        x0  = vis[b * Vn + vg];
        x1  = vis[b * Vn + vg + 1];
        c0  = w_text[vg];
        c1  = w_text[vg + 1];
        bv0 = bias[vg];
        bv1 = bias[vg + 1];
    }

    float Z0 = 0.f, Z1 = 0.f, N0 = 0.f, N1 = 0.f;

    __half2* erow = e + warp * Tn;

    // Main loop over T. s = x*w + y*c + bias; E = exp(tanh(s)).
#pragma unroll 8
    for (int i = 0; i < 32; i++) {
        int t = lane + 32 * i;
        float2 p = wy[t];
        float w = p.x, y = p.y;

        float s0 = fmaf(x0, w, fmaf(y, c0, bv0));
        float s1 = fmaf(x1, w, fmaf(y, c1, bv1));
        float E0 = fex2_approx(ftanh_approx(s0) * L2E);
        float E1 = fex2_approx(ftanh_approx(s1) * L2E);
        erow[t] = __floats2half2_rn(E0, E1);
        Z0 += E0;
        Z1 += E1;
        N0 = fmaf(E0, y, N0);
        N1 = fmaf(E1, y, N1);
    }

    // Warp reductions for Z and the text numerator
#pragma unroll
    for (int o = 16; o > 0; o >>= 1) {
        Z0 += __shfl_xor_sync(0xffffffffu, Z0, o);
        Z1 += __shfl_xor_sync(0xffffffffu, Z1, o);
        N0 += __shfl_xor_sync(0xffffffffu, N0, o);
        N1 += __shfl_xor_sync(0xffffffffu, N1, o);
    }

    if (lane == 0) {
        float iZ0 = 1.0f / Z0;
        float iZ1 = 1.0f / Z1;
        g_ts[b * Vn + v0 + vl]     = N0 * iZ0;
        g_ts[b * Vn + v0 + vl + 1] = N1 * iZ1;
        g[vl]     = x0 * iZ0;
        g[vl + 1] = x1 * iZ1;
    }
    __syncthreads();

    // Pass 2: visual partial per t from half2 slab
    float gr[VT];
#pragma unroll
    for (int vv = 0; vv < VT; vv++) gr[vv] = g[vv];

#pragma unroll
    for (int i = 0; i < 4; i++) {
        int t = tid + 256 * i;
        float acc = 0.f;
#pragma unroll
        for (int w8 = 0; w8 < 8; w8++) {
            float2 f = __half22float2(e[w8 * Tn + t]);
            acc = fmaf(f.x, gr[2 * w8], acc);
            acc = fmaf(f.y, gr[2 * w8 + 1], acc);
        }
        atomicAdd(&g_vs[b * Tn + t], acc);
    }
}

// ---------------------------------------------------------------------------
// Kernel 2: split-K GEMM  out_acc[b,c] += sum_k A[b,k] * W[c,k]
// A = g_vs with W_fv (k-slices 0..3), A = g_ts with W_ft (k-slices 4..7).
// Grid: (16 c-tiles, 8 k-slices). Block 256. CTA tile 128b x 64c, K=256/CTA.
// ---------------------------------------------------------------------------
#define KC 32

__global__ __launch_bounds__(256, 1) void gemm_split_kernel(
    const float* __restrict__ Wfv,  // [C, T]
    const float* __restrict__ Wft)  // [C, V]
{
    __shared__ float As[KC][128];
    __shared__ float Ws[KC][64];

    const int ctile = blockIdx.x;
    const int ks    = blockIdx.y;

    const float* A;
    const float* W;
    int k0;
    if (ks < 4) { A = g_vs; W = Wfv; k0 = ks * 256; }
    else        { A = g_ts; W = Wft; k0 = (ks - 4) * 256; }

    const int c0  = ctile * 64;
    const int tid = threadIdx.x;
    const int tx  = tid & 15;   // c group (4 columns)
    const int ty  = tid >> 4;   // b group (8 rows)

    float acc[8][4];
#pragma unroll
    for (int i = 0; i < 8; i++)
#pragma unroll
        for (int j = 0; j < 4; j++) acc[i][j] = 0.f;

    const int lb = tid >> 1;          // 0..127 (b row for A load)
    const int lk = (tid & 1) * 16;    // 0 or 16
    const int wc = tid >> 2;          // 0..63 (c row for W load)
    const int wk = (tid & 3) * 8;     // 0,8,16,24

    for (int kc = 0; kc < 256; kc += KC) {
        const float4* ap = (const float4*)(A + lb * Tn + k0 + kc + lk);
#pragma unroll
        for (int q = 0; q < 4; q++) {
            float4 v = ap[q];
            As[lk + q * 4 + 0][lb] = v.x;
            As[lk + q * 4 + 1][lb] = v.y;
            As[lk + q * 4 + 2][lb] = v.z;
            As[lk + q * 4 + 3][lb] = v.w;
        }
        const float4* wp = (const float4*)(W + (c0 + wc) * Tn + k0 + kc + wk);
#pragma unroll
        for (int q = 0; q < 2; q++) {
            float4 v = wp[q];
            Ws[wk + q * 4 + 0][wc] = v.x;
            Ws[wk + q * 4 + 1][wc] = v.y;
            Ws[wk + q * 4 + 2][wc] = v.z;
            Ws[wk + q * 4 + 3][wc] = v.w;
        }
        __syncthreads();

#pragma unroll
        for (int kk = 0; kk < KC; kk++) {
            float a[8], wr[4];
            *(float4*)&a[0] = *(const float4*)&As[kk][ty * 8];
            *(float4*)&a[4] = *(const float4*)&As[kk][ty * 8 + 4];
            *(float4*)&wr[0] = *(const float4*)&Ws[kk][tx * 4];
#pragma unroll
            for (int i = 0; i < 8; i++)
#pragma unroll
                for (int j = 0; j < 4; j++)
                    acc[i][j] = fmaf(a[i], wr[j], acc[i][j]);
        }
        __syncthreads();
    }

#pragma unroll
    for (int i = 0; i < 8; i++) {
        int bb = ty * 8 + i;
#pragma unroll
        for (int j = 0; j < 4; j++)
            atomicAdd(&g_acc[bb * Cn + c0 + tx * 4 + j], acc[i][j]);
    }
}

// ---------------------------------------------------------------------------
// Kernel 3: bias + relu epilogue
// ---------------------------------------------------------------------------
__global__ __launch_bounds__(256) void epilogue_kernel(
    const float* __restrict__ bfv,
    const float* __restrict__ bft,
    float* __restrict__ out)
{
    int i = blockIdx.x * 256 + threadIdx.x;
    int c = i & (Cn - 1);
    float v = g_acc[i] + bfv[c] + bft[c];
    out[i] = v > 0.f ? v : 0.f;
}

// ---------------------------------------------------------------------------
extern "C" void kernel_launch(void* const* d_in, const int* in_sizes, int n_in,
                              void* d_out, int out_size)
{
    const float* vis    = (const float*)d_in[0];
    const float* txt    = (const float*)d_in[1];
    const float* w_vis  = (const float*)d_in[2];
    const float* w_text = (const float*)d_in[3];
    const float* bias   = (const float*)d_in[4];
    const float* Wfv    = (const float*)d_in[5];
    const float* bfv    = (const float*)d_in[6];
    const float* Wft    = (const float*)d_in[7];
    const float* bft    = (const float*)d_in[8];
    float* out = (float*)d_out;

    void* vs_ptr = nullptr;
    void* acc_ptr = nullptr;
    cudaGetSymbolAddress(&vs_ptr, g_vs);
    cudaGetSymbolAddress(&acc_ptr, g_acc);
    cudaMemsetAsync(vs_ptr, 0, Bn * Tn * sizeof(float));
    cudaMemsetAsync(acc_ptr, 0, Bn * Cn * sizeof(float));

    // e (8*Tn half2 = 32KB) + wy (Tn float2 = 8KB) + g (VT floats)
    const int smem_bytes = 8 * Tn * (int)sizeof(__half2)
                         + Tn * (int)sizeof(float2)
                         + VT * (int)sizeof(float);
    cudaFuncSetAttribute(attn_pass_kernel,
                         cudaFuncAttributeMaxDynamicSharedMemorySize, smem_bytes);

    dim3 g1(Vn / VT, Bn);
    attn_pass_kernel<<<g1, 256, smem_bytes>>>(vis, txt, w_vis, w_text, bias);

    dim3 g2(16, 8);
    gemm_split_kernel<<<g2, 256>>>(Wfv, Wft);

    epilogue_kernel<<<(Bn * Cn) / 256, 256>>>(bfv, bft, out);
}

// round 5
// speedup vs baseline: 1.6765x; 1.6765x over previous
#include <cuda_runtime.h>
#include <cuda_bf16.h>
#include <cuda_fp16.h>

#define Bn 128
#define Vn 1024
#define Tn 1024
#define Cn 1024
#define VT 16   // v-columns per CTA in the attention kernel (8 warps x 2 cols)

// Scratch (allocation-free rule: __device__ globals).
// g_zero = [ g_vs (Bn*Tn) | g_acc (Bn*Cn) ]  -> single memset per launch.
__device__ float g_zero[Bn * Tn + Bn * Cn];
__device__ float g_ts[Bn * Vn];   // text_score, written exactly once (no memset needed)

__device__ __forceinline__ float fex2_approx(float x) {
    float r;
    asm("ex2.approx.f32 %0, %1;" : "=f"(r) : "f"(x));
    return r;
}

__device__ __forceinline__ float ftanh_approx(float x) {
    float r;
    asm("tanh.approx.f32 %0, %1;" : "=f"(r) : "f"(x));
    return r;
}

// Pack two f32 into one f16x2 register with a single SASS op.
__device__ __forceinline__ unsigned pack_f16x2(float lo, float hi) {
    unsigned p;
    asm("cvt.rn.f16x2.f32 %0, %1, %2;" : "=r"(p) : "f"(hi), "f"(lo));
    return p;
}

// ---------------------------------------------------------------------------
// Kernel 1: fused scores/tanh/softmax/reductions.
// Grid: (Vn/VT, Bn). Block: 256 threads (8 warps, 2 v-columns per warp).
// Pass 1: E = exp(tanh(s)) -> half2 slab, one pack + one STS.32 per elem-pair.
// Pass 2: visual partials via native HFMA2 (no conversions), RED into g_vs.
// SMEM: slab 32KB + wy 8KB + g2 32B -> 5 CTAs/SM.
// ---------------------------------------------------------------------------
extern __shared__ float smem_dyn[];

__global__ __launch_bounds__(256, 5) void attn_pass_kernel(
    const float* __restrict__ vis,     // [B, V]
    const float* __restrict__ txt,     // [B, T]
    const float* __restrict__ w_vis,   // [T]
    const float* __restrict__ w_text,  // [V]
    const float* __restrict__ bias)    // [V]
{
    __half2* e   = (__half2*)smem_dyn;                 // 8 warps x Tn (half2 = col pair)
    float2*  wy  = (float2*)(smem_dyn + 2 * 4096);     // Tn x (w, y)
    __half2* g2s = (__half2*)(wy + Tn);                // 8 packed (g0,g1) pairs

    float* g_vs = g_zero;

    const int b   = blockIdx.y;
    const int v0  = blockIdx.x * VT;
    const int tid = threadIdx.x;

    for (int i = tid; i < Tn; i += 256)
        wy[i] = make_float2(w_vis[i], txt[b * Tn + i]);
    __syncthreads();

    const int warp = tid >> 5;
    const int lane = tid & 31;
    const int vl   = warp * 2;

    const float L2E = 1.4426950408889634f;

    float x0, x1, c0, c1, bv0, bv1;
    {
        int vg = v0 + vl;
        x0  = vis[b * Vn + vg];
        x1  = vis[b * Vn + vg + 1];
        c0  = w_text[vg];
        c1  = w_text[vg + 1];
        bv0 = bias[vg];
        bv1 = bias[vg + 1];
    }

    float Z0 = 0.f, Z1 = 0.f, N0 = 0.f, N1 = 0.f;

    unsigned* erow = (unsigned*)(e + warp * Tn);

    // Main loop over T. s = x*w + y*c + bias; E = exp(tanh(s)).
#pragma unroll 8
    for (int i = 0; i < 32; i++) {
        int t = lane + 32 * i;
        float2 p = wy[t];
        float w = p.x, y = p.y;

        float s0 = fmaf(x0, w, fmaf(y, c0, bv0));
        float s1 = fmaf(x1, w, fmaf(y, c1, bv1));
        float E0 = fex2_approx(ftanh_approx(s0) * L2E);
        float E1 = fex2_approx(ftanh_approx(s1) * L2E);
        erow[t] = pack_f16x2(E0, E1);   // single F2FP + single STS.32
        Z0 += E0;
        Z1 += E1;
        N0 = fmaf(E0, y, N0);
        N1 = fmaf(E1, y, N1);
    }

    // Warp reductions for Z and the text numerator
#pragma unroll
    for (int o = 16; o > 0; o >>= 1) {
        Z0 += __shfl_xor_sync(0xffffffffu, Z0, o);
        Z1 += __shfl_xor_sync(0xffffffffu, Z1, o);
        N0 += __shfl_xor_sync(0xffffffffu, N0, o);
        N1 += __shfl_xor_sync(0xffffffffu, N1, o);
    }

    if (lane == 0) {
        float iZ0 = 1.0f / Z0;
        float iZ1 = 1.0f / Z1;
        g_ts[b * Vn + v0 + vl]     = N0 * iZ0;
        g_ts[b * Vn + v0 + vl + 1] = N1 * iZ1;
        g2s[warp] = __floats2half2_rn(x0 * iZ0, x1 * iZ1);
    }
    __syncthreads();

    // Pass 2: visual partial per t, native half2 FMA (no per-element cvt)
    __half2 gr[8];
#pragma unroll
    for (int w8 = 0; w8 < 8; w8++) gr[w8] = g2s[w8];

#pragma unroll
    for (int i = 0; i < 4; i++) {
        int t = tid + 256 * i;
        __half2 acc2 = __float2half2_rn(0.f);
#pragma unroll
        for (int w8 = 0; w8 < 8; w8++)
            acc2 = __hfma2(e[w8 * Tn + t], gr[w8], acc2);
        float acc = __low2float(acc2) + __high2float(acc2);
        atomicAdd(&g_vs[b * Tn + t], acc);
    }
}

// ---------------------------------------------------------------------------
// Kernel 2: split-K GEMM  out_acc[b,c] += sum_k A[b,k] * W[c,k]
// A = g_vs with W_fv (k-slices 0..3), A = g_ts with W_ft (k-slices 4..7).
// Grid: (16 c-tiles, 8 k-slices). Block 256. CTA tile 128b x 64c, K=256/CTA.
// ---------------------------------------------------------------------------
#define KC 32

__global__ __launch_bounds__(256, 1) void gemm_split_kernel(
    const float* __restrict__ Wfv,  // [C, T]
    const float* __restrict__ Wft)  // [C, V]
{
    __shared__ float As[KC][128];
    __shared__ float Ws[KC][64];

    float* g_vs  = g_zero;
    float* g_acc = g_zero + Bn * Tn;

    const int ctile = blockIdx.x;
    const int ks    = blockIdx.y;

    const float* A;
    const float* W;
    int k0;
    if (ks < 4) { A = g_vs; W = Wfv; k0 = ks * 256; }
    else        { A = g_ts; W = Wft; k0 = (ks - 4) * 256; }

    const int c0  = ctile * 64;
    const int tid = threadIdx.x;
    const int tx  = tid & 15;   // c group (4 columns)
    const int ty  = tid >> 4;   // b group (8 rows)

    float acc[8][4];
#pragma unroll
    for (int i = 0; i < 8; i++)
#pragma unroll
        for (int j = 0; j < 4; j++) acc[i][j] = 0.f;

    const int lb = tid >> 1;          // 0..127 (b row for A load)
    const int lk = (tid & 1) * 16;    // 0 or 16
    const int wc = tid >> 2;          // 0..63 (c row for W load)
    const int wk = (tid & 3) * 8;     // 0,8,16,24

    for (int kc = 0; kc < 256; kc += KC) {
        const float4* ap = (const float4*)(A + lb * Tn + k0 + kc + lk);
#pragma unroll
        for (int q = 0; q < 4; q++) {
            float4 v = ap[q];
            As[lk + q * 4 + 0][lb] = v.x;
            As[lk + q * 4 + 1][lb] = v.y;
            As[lk + q * 4 + 2][lb] = v.z;
            As[lk + q * 4 + 3][lb] = v.w;
        }
        const float4* wp = (const float4*)(W + (c0 + wc) * Tn + k0 + kc + wk);
#pragma unroll
        for (int q = 0; q < 2; q++) {
            float4 v = wp[q];
            Ws[wk + q * 4 + 0][wc] = v.x;
            Ws[wk + q * 4 + 1][wc] = v.y;
            Ws[wk + q * 4 + 2][wc] = v.z;
            Ws[wk + q * 4 + 3][wc] = v.w;
        }
        __syncthreads();

#pragma unroll
        for (int kk = 0; kk < KC; kk++) {
            float a[8], wr[4];
            *(float4*)&a[0] = *(const float4*)&As[kk][ty * 8];
            *(float4*)&a[4] = *(const float4*)&As[kk][ty * 8 + 4];
            *(float4*)&wr[0] = *(const float4*)&Ws[kk][tx * 4];
#pragma unroll
            for (int i = 0; i < 8; i++)
#pragma unroll
                for (int j = 0; j < 4; j++)
                    acc[i][j] = fmaf(a[i], wr[j], acc[i][j]);
        }
        __syncthreads();
    }

#pragma unroll
    for (int i = 0; i < 8; i++) {
        int bb = ty * 8 + i;
#pragma unroll
        for (int j = 0; j < 4; j++)
            atomicAdd(&g_acc[bb * Cn + c0 + tx * 4 + j], acc[i][j]);
    }
}

// ---------------------------------------------------------------------------
// Kernel 3: bias + relu epilogue
// ---------------------------------------------------------------------------
__global__ __launch_bounds__(256) void epilogue_kernel(
    const float* __restrict__ bfv,
    const float* __restrict__ bft,
    float* __restrict__ out)
{
    const float* g_acc = g_zero + Bn * Tn;
    int i = blockIdx.x * 256 + threadIdx.x;
    int c = i & (Cn - 1);
    float v = g_acc[i] + bfv[c] + bft[c];
    out[i] = v > 0.f ? v : 0.f;
}

// ---------------------------------------------------------------------------
extern "C" void kernel_launch(void* const* d_in, const int* in_sizes, int n_in,
                              void* d_out, int out_size)
{
    const float* vis    = (const float*)d_in[0];
    const float* txt    = (const float*)d_in[1];
    const float* w_vis  = (const float*)d_in[2];
    const float* w_text = (const float*)d_in[3];
    const float* bias   = (const float*)d_in[4];
    const float* Wfv    = (const float*)d_in[5];
    const float* bfv    = (const float*)d_in[6];
    const float* Wft    = (const float*)d_in[7];
    const float* bft    = (const float*)d_in[8];
    float* out = (float*)d_out;

    void* z_ptr = nullptr;
    cudaGetSymbolAddress(&z_ptr, g_zero);
    cudaMemsetAsync(z_ptr, 0, (Bn * Tn + Bn * Cn) * sizeof(float));

    // slab (8*Tn half2 = 32KB) + wy (Tn float2 = 8KB) + g2 (8 half2)
    const int smem_bytes = 8 * Tn * (int)sizeof(__half2)
                         + Tn * (int)sizeof(float2)
                         + 8 * (int)sizeof(__half2);
    cudaFuncSetAttribute(attn_pass_kernel,
                         cudaFuncAttributeMaxDynamicSharedMemorySize, smem_bytes);

    dim3 g1(Vn / VT, Bn);
    attn_pass_kernel<<<g1, 256, smem_bytes>>>(vis, txt, w_vis, w_text, bias);

    dim3 g2(16, 8);
    gemm_split_kernel<<<g2, 256>>>(Wfv, Wft);

    epilogue_kernel<<<(Bn * Cn) / 256, 256>>>(bfv, bft, out);
}

// round 8
// speedup vs baseline: 1.6960x; 1.0116x over previous
#include <cuda_runtime.h>
#include <cuda_bf16.h>
#include <cuda_fp16.h>

#define Bn 128
#define Vn 1024
#define Tn 1024
#define Cn 1024
#define VT 16   // v-columns per CTA in the attention kernel (8 warps x 2 cols)

typedef unsigned long long u64;

// Scratch (allocation-free rule: __device__ globals).
// g_zero = [ g_vs (Bn*Tn) | g_acc (Bn*Cn) ]  -> single memset per launch.
__device__ float g_zero[Bn * Tn + Bn * Cn];
__device__ float g_ts[Bn * Vn];   // text_score, written exactly once

__device__ __forceinline__ float fex2_approx(float x) {
    float r;
    asm("ex2.approx.f32 %0, %1;" : "=f"(r) : "f"(x));
    return r;
}

__device__ __forceinline__ float ftanh_approx(float x) {
    float r;
    asm("tanh.approx.f32 %0, %1;" : "=f"(r) : "f"(x));
    return r;
}

// Pack two f32 into one f16x2 register with a single SASS op.
__device__ __forceinline__ unsigned pack_f16x2(float lo, float hi) {
    unsigned p;
    asm("cvt.rn.f16x2.f32 %0, %1, %2;" : "=r"(p) : "f"(hi), "f"(lo));
    return p;
}

// ---- packed fp32x2 (SASS FFMA2) helpers ----
__device__ __forceinline__ u64 f2fma(u64 a, u64 b, u64 c) {
    u64 d;
    asm("fma.rn.f32x2 %0, %1, %2, %3;" : "=l"(d) : "l"(a), "l"(b), "l"(c));
    return d;
}
__device__ __forceinline__ u64 f2pack(float lo, float hi) {
    u64 d;
    asm("mov.b64 %0, {%1, %2};" : "=l"(d) : "f"(lo), "f"(hi));
    return d;
}
__device__ __forceinline__ float2 f2unpack(u64 v) {
    float2 r;
    asm("mov.b64 {%0, %1}, %2;" : "=f"(r.x), "=f"(r.y) : "l"(v));
    return r;
}

// ---------------------------------------------------------------------------
// Kernel 1: fused scores/tanh/softmax/reductions.  (R5 config — proven)
// Grid: (Vn/VT, Bn). Block: 256 threads (8 warps, 2 v-columns per warp).
// Pass 1: all-f32 math (tanh.approx.f32 + ex2.approx.f32), f16 STORAGE only.
// Pass 2: visual partials via native HFMA2, RED into g_vs.
// SMEM: slab 32KB + wy 8KB + g2 32B -> 5 CTAs/SM.
// ---------------------------------------------------------------------------
extern __shared__ float smem_dyn[];

__global__ __launch_bounds__(256, 5) void attn_pass_kernel(
    const float* __restrict__ vis,     // [B, V]
    const float* __restrict__ txt,     // [B, T]
    const float* __restrict__ w_vis,   // [T]
    const float* __restrict__ w_text,  // [V]
    const float* __restrict__ bias)    // [V]
{
    __half2* e   = (__half2*)smem_dyn;                 // 8 warps x Tn (half2 = col pair)
    float2*  wy  = (float2*)(smem_dyn + 2 * 4096);     // Tn x (w, y)
    __half2* g2s = (__half2*)(wy + Tn);                // 8 packed (g0,g1) pairs

    float* g_vs = g_zero;

    const int b   = blockIdx.y;
    const int v0  = blockIdx.x * VT;
    const int tid = threadIdx.x;

    for (int i = tid; i < Tn; i += 256)
        wy[i] = make_float2(w_vis[i], txt[b * Tn + i]);
    __syncthreads();

    const int warp = tid >> 5;
    const int lane = tid & 31;
    const int vl   = warp * 2;

    const float L2E = 1.4426950408889634f;

    float x0, x1, c0, c1, bv0, bv1;
    {
        int vg = v0 + vl;
        x0  = vis[b * Vn + vg];
        x1  = vis[b * Vn + vg + 1];
        c0  = w_text[vg];
        c1  = w_text[vg + 1];
        bv0 = bias[vg];
        bv1 = bias[vg + 1];
    }

    float Z0 = 0.f, Z1 = 0.f, N0 = 0.f, N1 = 0.f;

    unsigned* erow = (unsigned*)(e + warp * Tn);

    // Main loop over T. s = x*w + y*c + bias; E = exp(tanh(s)).
#pragma unroll 8
    for (int i = 0; i < 32; i++) {
        int t = lane + 32 * i;
        float2 p = wy[t];
        float w = p.x, y = p.y;

        float s0 = fmaf(x0, w, fmaf(y, c0, bv0));
        float s1 = fmaf(x1, w, fmaf(y, c1, bv1));
        float E0 = fex2_approx(ftanh_approx(s0) * L2E);
        float E1 = fex2_approx(ftanh_approx(s1) * L2E);
        erow[t] = pack_f16x2(E0, E1);   // single F2FP + single STS.32
        Z0 += E0;
        Z1 += E1;
        N0 = fmaf(E0, y, N0);
        N1 = fmaf(E1, y, N1);
    }

    // Warp reductions for Z and the text numerator
#pragma unroll
    for (int o = 16; o > 0; o >>= 1) {
        Z0 += __shfl_xor_sync(0xffffffffu, Z0, o);
        Z1 += __shfl_xor_sync(0xffffffffu, Z1, o);
        N0 += __shfl_xor_sync(0xffffffffu, N0, o);
        N1 += __shfl_xor_sync(0xffffffffu, N1, o);
    }

    if (lane == 0) {
        float iZ0 = 1.0f / Z0;
        float iZ1 = 1.0f / Z1;
        g_ts[b * Vn + v0 + vl]     = N0 * iZ0;
        g_ts[b * Vn + v0 + vl + 1] = N1 * iZ1;
        g2s[warp] = __floats2half2_rn(x0 * iZ0, x1 * iZ1);
    }
    __syncthreads();

    // Pass 2: visual partial per t, native half2 FMA (no per-element cvt)
    __half2 gr[8];
#pragma unroll
    for (int w8 = 0; w8 < 8; w8++) gr[w8] = g2s[w8];

#pragma unroll
    for (int i = 0; i < 4; i++) {
        int t = tid + 256 * i;
        __half2 acc2 = __float2half2_rn(0.f);
#pragma unroll
        for (int w8 = 0; w8 < 8; w8++)
            acc2 = __hfma2(e[w8 * Tn + t], gr[w8], acc2);
        float acc = __low2float(acc2) + __high2float(acc2);
        atomicAdd(&g_vs[b * Tn + t], acc);
    }
}

// ---------------------------------------------------------------------------
// Kernel 2: split-K GEMM with packed fma.rn.f32x2 (FFMA2).
// out_acc[b,c] += sum_k A[b,k] * W[c,k]
// A = g_vs with W_fv (k-slices 0..3), A = g_ts with W_ft (k-slices 4..7).
// Grid: (16 c-tiles, 8 k-slices). Block 256. CTA tile 128b x 64c, K=256/CTA.
// Microtile: 4 b-row-PAIRS (f32x2) x 4 cols -> 16 FFMA2/kk instead of 32 FFMA.
// ---------------------------------------------------------------------------
#define KC 32

__global__ __launch_bounds__(256, 1) void gemm_split_kernel(
    const float* __restrict__ Wfv,  // [C, T]
    const float* __restrict__ Wft)  // [C, V]
{
    __shared__ float As[KC][128];
    __shared__ float Ws[KC][64];

    float* g_vs  = g_zero;
    float* g_acc = g_zero + Bn * Tn;

    const int ctile = blockIdx.x;
    const int ks    = blockIdx.y;

    const float* A;
    const float* W;
    int k0;
    if (ks < 4) { A = g_vs; W = Wfv; k0 = ks * 256; }
    else        { A = g_ts; W = Wft; k0 = (ks - 4) * 256; }

    const int c0  = ctile * 64;
    const int tid = threadIdx.x;
    const int tx  = tid & 15;   // c group (4 columns)
    const int ty  = tid >> 4;   // b group (8 rows = 4 row-pairs)

    u64 acc2[4][4];
#pragma unroll
    for (int i = 0; i < 4; i++)
#pragma unroll
        for (int j = 0; j < 4; j++) acc2[i][j] = 0ull;

    const int lb = tid >> 1;          // 0..127 (b row for A load)
    const int lk = (tid & 1) * 16;    // 0 or 16
    const int wc = tid >> 2;          // 0..63 (c row for W load)
    const int wk = (tid & 3) * 8;     // 0,8,16,24

    for (int kc = 0; kc < 256; kc += KC) {
        const float4* ap = (const float4*)(A + lb * Tn + k0 + kc + lk);
#pragma unroll
        for (int q = 0; q < 4; q++) {
            float4 v = ap[q];
            As[lk + q * 4 + 0][lb] = v.x;
            As[lk + q * 4 + 1][lb] = v.y;
            As[lk + q * 4 + 2][lb] = v.z;
            As[lk + q * 4 + 3][lb] = v.w;
        }
        const float4* wp = (const float4*)(W + (c0 + wc) * Tn + k0 + kc + wk);
#pragma unroll
        for (int q = 0; q < 2; q++) {
            float4 v = wp[q];
            Ws[wk + q * 4 + 0][wc] = v.x;
            Ws[wk + q * 4 + 1][wc] = v.y;
            Ws[wk + q * 4 + 2][wc] = v.z;
            Ws[wk + q * 4 + 3][wc] = v.w;
        }
        __syncthreads();

#pragma unroll
        for (int kk = 0; kk < KC; kk++) {
            // A row-pairs read directly as 64-bit lanes (32B-aligned)
            u64 a2[4];
            const u64* ap2 = (const u64*)&As[kk][ty * 8];
#pragma unroll
            for (int i = 0; i < 4; i++) a2[i] = ap2[i];

            float wr[4];
            *(float4*)&wr[0] = *(const float4*)&Ws[kk][tx * 4];
            u64 w2[4];
#pragma unroll
            for (int j = 0; j < 4; j++) w2[j] = f2pack(wr[j], wr[j]);

#pragma unroll
            for (int i = 0; i < 4; i++)
#pragma unroll
                for (int j = 0; j < 4; j++)
                    acc2[i][j] = f2fma(a2[i], w2[j], acc2[i][j]);
        }
        __syncthreads();
    }

#pragma unroll
    for (int i = 0; i < 4; i++) {
        int bb = ty * 8 + 2 * i;
#pragma unroll
        for (int j = 0; j < 4; j++) {
            float2 f = f2unpack(acc2[i][j]);
            atomicAdd(&g_acc[(bb)     * Cn + c0 + tx * 4 + j], f.x);
            atomicAdd(&g_acc[(bb + 1) * Cn + c0 + tx * 4 + j], f.y);
        }
    }
}

// ---------------------------------------------------------------------------
// Kernel 3: bias + relu epilogue
// ---------------------------------------------------------------------------
__global__ __launch_bounds__(256) void epilogue_kernel(
    const float* __restrict__ bfv,
    const float* __restrict__ bft,
    float* __restrict__ out)
{
    const float* g_acc = g_zero + Bn * Tn;
    int i = blockIdx.x * 256 + threadIdx.x;
    int c = i & (Cn - 1);
    float v = g_acc[i] + bfv[c] + bft[c];
    out[i] = v > 0.f ? v : 0.f;
}

// ---------------------------------------------------------------------------
extern "C" void kernel_launch(void* const* d_in, const int* in_sizes, int n_in,
                              void* d_out, int out_size)
{
    const float* vis    = (const float*)d_in[0];
    const float* txt    = (const float*)d_in[1];
    const float* w_vis  = (const float*)d_in[2];
    const float* w_text = (const float*)d_in[3];
    const float* bias   = (const float*)d_in[4];
    const float* Wfv    = (const float*)d_in[5];
    const float* bfv    = (const float*)d_in[6];
    const float* Wft    = (const float*)d_in[7];
    const float* bft    = (const float*)d_in[8];
    float* out = (float*)d_out;

    void* z_ptr = nullptr;
    cudaGetSymbolAddress(&z_ptr, g_zero);
    cudaMemsetAsync(z_ptr, 0, (Bn * Tn + Bn * Cn) * sizeof(float));

    // slab (8*Tn half2 = 32KB) + wy (Tn float2 = 8KB) + g2 (8 half2)
    const int smem_bytes = 8 * Tn * (int)sizeof(__half2)
                         + Tn * (int)sizeof(float2)
                         + 8 * (int)sizeof(__half2);
    cudaFuncSetAttribute(attn_pass_kernel,
                         cudaFuncAttributeMaxDynamicSharedMemorySize, smem_bytes);

    dim3 g1(Vn / VT, Bn);
    attn_pass_kernel<<<g1, 256, smem_bytes>>>(vis, txt, w_vis, w_text, bias);

    dim3 g2(16, 8);
    gemm_split_kernel<<<g2, 256>>>(Wfv, Wft);

    epilogue_kernel<<<(Bn * Cn) / 256, 256>>>(bfv, bft, out);
}

// round 10
// speedup vs baseline: 1.7402x; 1.0260x over previous
#include <cuda_runtime.h>
#include <cuda_bf16.h>
#include <cuda_fp16.h>

#define Bn 128
#define Vn 1024
#define Tn 1024
#define Cn 1024
#define VT 16   // v-columns per CTA in the attention kernel (8 warps x 2 cols)

typedef unsigned long long u64;

// Scratch (allocation-free rule: __device__ globals).
// g_zero = [ g_vs (Bn*Tn) | g_acc (Bn*Cn) ]  -> single memset per launch.
__device__ float g_zero[Bn * Tn + Bn * Cn];
__device__ float g_ts[Bn * Vn];   // text_score, written exactly once

__device__ __forceinline__ float fex2_approx(float x) {
    float r;
    asm("ex2.approx.f32 %0, %1;" : "=f"(r) : "f"(x));
    return r;
}

__device__ __forceinline__ float ftanh_approx(float x) {
    float r;
    asm("tanh.approx.f32 %0, %1;" : "=f"(r) : "f"(x));
    return r;
}

// Pack two f32 into one f16x2 register with a single SASS op.
__device__ __forceinline__ unsigned pack_f16x2(float lo, float hi) {
    unsigned p;
    asm("cvt.rn.f16x2.f32 %0, %1, %2;" : "=r"(p) : "f"(hi), "f"(lo));
    return p;
}

// ---- packed fp32x2 (SASS FFMA2) helpers ----
__device__ __forceinline__ u64 f2fma(u64 a, u64 b, u64 c) {
    u64 d;
    asm("fma.rn.f32x2 %0, %1, %2, %3;" : "=l"(d) : "l"(a), "l"(b), "l"(c));
    return d;
}
__device__ __forceinline__ u64 f2pack(float lo, float hi) {
    u64 d;
    asm("mov.b64 %0, {%1, %2};" : "=l"(d) : "f"(lo), "f"(hi));
    return d;
}
__device__ __forceinline__ float2 f2unpack(u64 v) {
    float2 r;
    asm("mov.b64 {%0, %1}, %2;" : "=f"(r.x), "=f"(r.y) : "l"(v));
    return r;
}

// ---------------------------------------------------------------------------
// Kernel 1: fused scores/tanh/softmax/reductions.  (R5/R8 proven config)
// ALL transcendental math in f32 (tanh.approx.f32 + ex2.approx.f32);
// f16 used for STORAGE and linear pass-2 FMAs only.
// Grid: (Vn/VT, Bn). Block: 256 threads (8 warps, 2 v-columns per warp).
// SMEM: slab 32KB + wy 8KB + g2 32B -> 5 CTAs/SM.
// ---------------------------------------------------------------------------
extern __shared__ float smem_dyn[];

__global__ __launch_bounds__(256, 5) void attn_pass_kernel(
    const float* __restrict__ vis,     // [B, V]
    const float* __restrict__ txt,     // [B, T]
    const float* __restrict__ w_vis,   // [T]
    const float* __restrict__ w_text,  // [V]
    const float* __restrict__ bias)    // [V]
{
    __half2* e   = (__half2*)smem_dyn;                 // 8 warps x Tn (half2 = col pair)
    float2*  wy  = (float2*)(smem_dyn + 2 * 4096);     // Tn x (w, y)
    __half2* g2s = (__half2*)(wy + Tn);                // 8 packed (g0,g1) pairs

    float* g_vs = g_zero;

    const int b   = blockIdx.y;
    const int v0  = blockIdx.x * VT;
    const int tid = threadIdx.x;

    for (int i = tid; i < Tn; i += 256)
        wy[i] = make_float2(w_vis[i], txt[b * Tn + i]);
    __syncthreads();

    const int warp = tid >> 5;
    const int lane = tid & 31;
    const int vl   = warp * 2;

    const float L2E = 1.4426950408889634f;

    float x0, x1, c0, c1, bv0, bv1;
    {
        int vg = v0 + vl;
        x0  = vis[b * Vn + vg];
        x1  = vis[b * Vn + vg + 1];
        c0  = w_text[vg];
        c1  = w_text[vg + 1];
        bv0 = bias[vg];
        bv1 = bias[vg + 1];
    }

    float Z0 = 0.f, Z1 = 0.f, N0 = 0.f, N1 = 0.f;

    unsigned* erow = (unsigned*)(e + warp * Tn);

    // Main loop over T. s = x*w + y*c + bias; E = exp(tanh(s)), all f32.
#pragma unroll 8
    for (int i = 0; i < 32; i++) {
        int t = lane + 32 * i;
        float2 p = wy[t];
        float w = p.x, y = p.y;

        float s0 = fmaf(x0, w, fmaf(y, c0, bv0));
        float s1 = fmaf(x1, w, fmaf(y, c1, bv1));
        float E0 = fex2_approx(ftanh_approx(s0) * L2E);
        float E1 = fex2_approx(ftanh_approx(s1) * L2E);
        erow[t] = pack_f16x2(E0, E1);   // single F2FP + single STS.32
        Z0 += E0;
        Z1 += E1;
        N0 = fmaf(E0, y, N0);
        N1 = fmaf(E1, y, N1);
    }

    // Warp reductions for Z and the text numerator
#pragma unroll
    for (int o = 16; o > 0; o >>= 1) {
        Z0 += __shfl_xor_sync(0xffffffffu, Z0, o);
        Z1 += __shfl_xor_sync(0xffffffffu, Z1, o);
        N0 += __shfl_xor_sync(0xffffffffu, N0, o);
        N1 += __shfl_xor_sync(0xffffffffu, N1, o);
    }

    if (lane == 0) {
        float iZ0 = 1.0f / Z0;
        float iZ1 = 1.0f / Z1;
        g_ts[b * Vn + v0 + vl]     = N0 * iZ0;
        g_ts[b * Vn + v0 + vl + 1] = N1 * iZ1;
        g2s[warp] = __floats2half2_rn(x0 * iZ0, x1 * iZ1);
    }
    __syncthreads();

    // Pass 2: visual partial per t, native half2 FMA (no per-element cvt)
    __half2 gr[8];
#pragma unroll
    for (int w8 = 0; w8 < 8; w8++) gr[w8] = g2s[w8];

#pragma unroll
    for (int i = 0; i < 4; i++) {
        int t = tid + 256 * i;
        __half2 acc2 = __float2half2_rn(0.f);
#pragma unroll
        for (int w8 = 0; w8 < 8; w8++)
            acc2 = __hfma2(e[w8 * Tn + t], gr[w8], acc2);
        float acc = __low2float(acc2) + __high2float(acc2);
        atomicAdd(&g_vs[b * Tn + t], acc);
    }
}

// ---------------------------------------------------------------------------
// Kernel 2: split-K GEMM, double-buffered, full-wave grid.
// out_acc[b,c] += sum_k A[b,k] * W[c,k]
// Grid: (16 c-tiles, 16 k-slices) = 256 CTAs. K=128/CTA, KC=32, 4 iters.
// A = g_vs + W_fv (ks 0..7), A = g_ts + W_ft (ks 8..15).
// Microtile: 4 b-row-pairs (FFMA2) x 4 cols.
// ---------------------------------------------------------------------------
#define KC 32

__global__ __launch_bounds__(256, 1) void gemm_split_kernel(
    const float* __restrict__ Wfv,  // [C, T]
    const float* __restrict__ Wft)  // [C, V]
{
    __shared__ float As[2][KC][128];
    __shared__ float Ws[2][KC][64];

    float* g_vs  = g_zero;
    float* g_acc = g_zero + Bn * Tn;

    const int ctile = blockIdx.x;
    const int ks    = blockIdx.y;

    const float* A;
    const float* W;
    int k0;
    if (ks < 8) { A = g_vs; W = Wfv; k0 = ks * 128; }
    else        { A = g_ts; W = Wft; k0 = (ks - 8) * 128; }

    const int c0  = ctile * 64;
    const int tid = threadIdx.x;
    const int tx  = tid & 15;   // c group (4 columns)
    const int ty  = tid >> 4;   // b group (8 rows = 4 row-pairs)

    u64 acc2[4][4];
#pragma unroll
    for (int i = 0; i < 4; i++)
#pragma unroll
        for (int j = 0; j < 4; j++) acc2[i][j] = 0ull;

    const int lb = tid >> 1;          // 0..127 (b row for A load)
    const int lk = (tid & 1) * 16;    // 0 or 16
    const int wc = tid >> 2;          // 0..63 (c row for W load)
    const int wk = (tid & 3) * 8;     // 0,8,16,24

    const float* aptr = A + lb * Tn + k0 + lk;
    const float* wptr = W + (c0 + wc) * Tn + k0 + wk;

    float4 ra[4], rw[2];

    // Preload iteration 0
#pragma unroll
    for (int q = 0; q < 4; q++) ra[q] = ((const float4*)aptr)[q];
#pragma unroll
    for (int q = 0; q < 2; q++) rw[q] = ((const float4*)wptr)[q];

    // Stage into buffer 0
#pragma unroll
    for (int q = 0; q < 4; q++) {
        As[0][lk + q * 4 + 0][lb] = ra[q].x;
        As[0][lk + q * 4 + 1][lb] = ra[q].y;
        As[0][lk + q * 4 + 2][lb] = ra[q].z;
        As[0][lk + q * 4 + 3][lb] = ra[q].w;
    }
#pragma unroll
    for (int q = 0; q < 2; q++) {
        Ws[0][wk + q * 4 + 0][wc] = rw[q].x;
        Ws[0][wk + q * 4 + 1][wc] = rw[q].y;
        Ws[0][wk + q * 4 + 2][wc] = rw[q].z;
        Ws[0][wk + q * 4 + 3][wc] = rw[q].w;
    }
    __syncthreads();

#pragma unroll
    for (int it = 0; it < 4; it++) {
        // Prefetch next slice into registers (overlaps with compute below)
        if (it < 3) {
            const float4* ap = (const float4*)(aptr + (it + 1) * KC);
            const float4* wp = (const float4*)(wptr + (it + 1) * KC);
#pragma unroll
            for (int q = 0; q < 4; q++) ra[q] = ap[q];
#pragma unroll
            for (int q = 0; q < 2; q++) rw[q] = wp[q];
        }

        const int buf = it & 1;
#pragma unroll
        for (int kk = 0; kk < KC; kk++) {
            u64 a2[4];
            const u64* ap2 = (const u64*)&As[buf][kk][ty * 8];
#pragma unroll
            for (int i = 0; i < 4; i++) a2[i] = ap2[i];

            float wr[4];
            *(float4*)&wr[0] = *(const float4*)&Ws[buf][kk][tx * 4];
            u64 w2[4];
#pragma unroll
            for (int j = 0; j < 4; j++) w2[j] = f2pack(wr[j], wr[j]);

#pragma unroll
            for (int i = 0; i < 4; i++)
#pragma unroll
                for (int j = 0; j < 4; j++)
                    acc2[i][j] = f2fma(a2[i], w2[j], acc2[i][j]);
        }

        if (it < 3) {
            const int nb = (it + 1) & 1;
#pragma unroll
            for (int q = 0; q < 4; q++) {
                As[nb][lk + q * 4 + 0][lb] = ra[q].x;
                As[nb][lk + q * 4 + 1][lb] = ra[q].y;
                As[nb][lk + q * 4 + 2][lb] = ra[q].z;
                As[nb][lk + q * 4 + 3][lb] = ra[q].w;
            }
#pragma unroll
            for (int q = 0; q < 2; q++) {
                Ws[nb][wk + q * 4 + 0][wc] = rw[q].x;
                Ws[nb][wk + q * 4 + 1][wc] = rw[q].y;
                Ws[nb][wk + q * 4 + 2][wc] = rw[q].z;
                Ws[nb][wk + q * 4 + 3][wc] = rw[q].w;
            }
            __syncthreads();
        }
    }

#pragma unroll
    for (int i = 0; i < 4; i++) {
        int bb = ty * 8 + 2 * i;
#pragma unroll
        for (int j = 0; j < 4; j++) {
            float2 f = f2unpack(acc2[i][j]);
            atomicAdd(&g_acc[(bb)     * Cn + c0 + tx * 4 + j], f.x);
            atomicAdd(&g_acc[(bb + 1) * Cn + c0 + tx * 4 + j], f.y);
        }
    }
}

// ---------------------------------------------------------------------------
// Kernel 3: bias + relu epilogue
// ---------------------------------------------------------------------------
__global__ __launch_bounds__(256) void epilogue_kernel(
    const float* __restrict__ bfv,
    const float* __restrict__ bft,
    float* __restrict__ out)
{
    const float* g_acc = g_zero + Bn * Tn;
    int i = blockIdx.x * 256 + threadIdx.x;
    int c = i & (Cn - 1);
    float v = g_acc[i] + bfv[c] + bft[c];
    out[i] = v > 0.f ? v : 0.f;
}

// ---------------------------------------------------------------------------
extern "C" void kernel_launch(void* const* d_in, const int* in_sizes, int n_in,
                              void* d_out, int out_size)
{
    const float* vis    = (const float*)d_in[0];
    const float* txt    = (const float*)d_in[1];
    const float* w_vis  = (const float*)d_in[2];
    const float* w_text = (const float*)d_in[3];
    const float* bias   = (const float*)d_in[4];
    const float* Wfv    = (const float*)d_in[5];
    const float* bfv    = (const float*)d_in[6];
    const float* Wft    = (const float*)d_in[7];
    const float* bft    = (const float*)d_in[8];
    float* out = (float*)d_out;

    void* z_ptr = nullptr;
    cudaGetSymbolAddress(&z_ptr, g_zero);
    cudaMemsetAsync(z_ptr, 0, (Bn * Tn + Bn * Cn) * sizeof(float));

    // slab (8*Tn half2 = 32KB) + wy (Tn float2 = 8KB) + g2 (8 half2)
    const int smem_bytes = 8 * Tn * (int)sizeof(__half2)
                         + Tn * (int)sizeof(float2)
                         + 8 * (int)sizeof(__half2);
    cudaFuncSetAttribute(attn_pass_kernel,
                         cudaFuncAttributeMaxDynamicSharedMemorySize, smem_bytes);

    dim3 g1(Vn / VT, Bn);
    attn_pass_kernel<<<g1, 256, smem_bytes>>>(vis, txt, w_vis, w_text, bias);

    dim3 g2(16, 16);
    gemm_split_kernel<<<g2, 256>>>(Wfv, Wft);

    epilogue_kernel<<<(Bn * Cn) / 256, 256>>>(bfv, bft, out);
}